// round 7
// baseline (speedup 1.0000x reference)
#include <cuda_runtime.h>
#include <cuda_bf16.h>
#include <stdint.h>

// Rules_67619965108887: out[row, r] = f(x[i0])*f(x[5+i1])*f(x[10+i2]),
// r = i0*25 + i1*5 + i2, f(v) = (v==0)?1:v.
//
// R6: warp-shuffle kernel, 4 contiguous rows per warp, fully unrolled.
// No smem, no barriers, no grid-stride loop. 4 up-front predicated LDG.32
// (MLP=4), then 4 independent row pipelines (high ILP):
//   p = shfl(xv,lane/5) * shfl(xv,5+lane%5)            (lanes 0..24 valid)
//   pass t: out[row*125 + lane+32t] = shfl(p,d_t)*shfl(xv,c_t)
// 1024 blocks x 256 thr -> 8192 warps, ~87% occupancy (R5 was capped at 50%).

static constexpr int F = 15;
static constexpr int R = 125;
static constexpr int THREADS = 256;
static constexpr int ROWS_PER_WARP = 4;
static constexpr unsigned FULL = 0xFFFFFFFFu;

__global__ __launch_bounds__(THREADS)
void Rules_67619965108887_kernel(const float* __restrict__ x,
                                 float* __restrict__ out,
                                 int n_rows) {
    const int lane = threadIdx.x & 31;
    const int gw   = (int)((blockIdx.x * blockDim.x + threadIdx.x) >> 5);
    const int row0 = gw * ROWS_PER_WARP;
    if (row0 >= n_rows) return;

    // ---- loop-invariant per-lane shuffle sources ----
    const int a_src = lane / 5;                 // p-build: a lane
    const int b_src = 5 + (lane - a_src * 5);   // p-build: b lane
    int d_t[4], c_src[4];
#pragma unroll
    for (int t = 0; t < 4; t++) {
        const int r = lane + 32 * t;
        const int d = r / 5;
        d_t[t]   = d;                  // p source lane (valid while r < 125)
        c_src[t] = 10 + (r - d * 5);   // xv source lane for c factor
    }
    const bool last_ok = (lane < R - 96);  // pass 3: r = lane+96 < 125

    // ---- batch the 4 row loads up front (MLP=4) ----
    const bool ld = (lane < F);
    const float* __restrict__ xb = x + (long long)row0 * F + lane;
    float xv[ROWS_PER_WARP];
#pragma unroll
    for (int k = 0; k < ROWS_PER_WARP; k++) {
        xv[k] = 1.0f;
        if (ld && row0 + k < n_rows) xv[k] = __ldg(xb + k * F);
    }
#pragma unroll
    for (int k = 0; k < ROWS_PER_WARP; k++) {
        xv[k] = (xv[k] == 0.0f) ? 1.0f : xv[k];
    }

    // ---- 4 independent row pipelines ----
    float* __restrict__ ob = out + (long long)row0 * R + lane;
#pragma unroll
    for (int k = 0; k < ROWS_PER_WARP; k++) {
        if (row0 + k >= n_rows) break;
        const float v = xv[k];
        const float p = __shfl_sync(FULL, v, a_src) * __shfl_sync(FULL, v, b_src);
        float* __restrict__ o = ob + k * R;

        const float P0 = __shfl_sync(FULL, p, d_t[0]);
        const float C0 = __shfl_sync(FULL, v, c_src[0]);
        o[0] = P0 * C0;
        const float P1 = __shfl_sync(FULL, p, d_t[1]);
        const float C1 = __shfl_sync(FULL, v, c_src[1]);
        o[32] = P1 * C1;
        const float P2 = __shfl_sync(FULL, p, d_t[2]);
        const float C2 = __shfl_sync(FULL, v, c_src[2]);
        o[64] = P2 * C2;
        const float P3 = __shfl_sync(FULL, p, d_t[3]);
        const float C3 = __shfl_sync(FULL, v, c_src[3]);
        if (last_ok) o[96] = P3 * C3;
    }
}

extern "C" void kernel_launch(void* const* d_in, const int* in_sizes, int n_in,
                              void* d_out, int out_size) {
    const float* x = (const float*)d_in[0];
    float* out = (float*)d_out;

    const int n_rows = in_sizes[0] / F;  // B*S = 32768
    const int warps_needed = (n_rows + ROWS_PER_WARP - 1) / ROWS_PER_WARP;  // 8192
    const int grid = (warps_needed * 32 + THREADS - 1) / THREADS;           // 1024

    Rules_67619965108887_kernel<<<grid, THREADS>>>(x, out, n_rows);
}